// round 2
// baseline (speedup 1.0000x reference)
#include <cuda_runtime.h>
#include <math.h>
#include <stdint.h>

#define NN 150000
#define FD 602
#define HD 128
#define CD 41

// Scratch (device globals: no allocation allowed in kernel_launch)
__device__ float g_P[(size_t)NN * HD];     // features @ W1^T
__device__ float g_h1[(size_t)NN * HD];    // relu(avg4(P))
__device__ float g_Q[(size_t)NN * HD];     // h1 @ W2^T
__device__ float g_W1T[FD * HD];           // W1 transposed, tf32-rounded
__device__ float g_W2T[HD * HD];           // W2 transposed, tf32-rounded

__device__ __forceinline__ float tf32r(float x) {
    unsigned u;
    asm("cvt.rna.tf32.f32 %0, %1;" : "=r"(u) : "f"(x));
    return __uint_as_float(u);
}

__device__ __forceinline__ void mma8(float* c, const float* a, float b0, float b1) {
    asm volatile(
        "mma.sync.aligned.m16n8k8.row.col.f32.tf32.tf32.f32 "
        "{%0,%1,%2,%3}, {%4,%5,%6,%7}, {%8,%9}, {%0,%1,%2,%3};\n"
        : "+f"(c[0]), "+f"(c[1]), "+f"(c[2]), "+f"(c[3])
        : "r"(__float_as_uint(a[0])), "r"(__float_as_uint(a[1])),
          "r"(__float_as_uint(a[2])), "r"(__float_as_uint(a[3])),
          "r"(__float_as_uint(b0)), "r"(__float_as_uint(b1)));
}

// BT[k][n] = tf32(W[n][k]);  which: 0 -> g_W1T (K=602), 1 -> g_W2T (K=128)
__global__ __launch_bounds__(256)
void k_prep_bt(const float* __restrict__ W, int K, int which) {
    int idx = blockIdx.x * 256 + threadIdx.x;
    if (idx >= K * HD) return;
    int n = idx & (HD - 1), k = idx >> 7;
    float* dst = (which == 0) ? g_W1T : g_W2T;
    dst[idx] = tf32r(W[n * K + k]);
}

// C[M][128] = A[M][K] @ BT[K][128], tf32 tensor-core GEMM.
// mode 0: A=features(param), BT=g_W1T, C=g_P
// mode 1: A=g_h1,            BT=g_W2T, C=g_Q
__global__ __launch_bounds__(256, 2)
void k_gemm_tf32(const float* __restrict__ Aext, int M, int K, int mode) {
    const float* __restrict__ A  = (mode == 0) ? Aext : g_h1;
    const float* __restrict__ BT = (mode == 0) ? g_W1T : g_W2T;
    float* __restrict__ C        = (mode == 0) ? g_P : g_Q;

    __shared__ float As[128][17];   // [m][k], padded
    __shared__ float Bs[16][136];   // [k][n], padded for conflict-free frag reads

    int tid = threadIdx.x;
    int m0 = blockIdx.x * 128;
    int wid = tid >> 5, lane = tid & 31;
    int wm = (wid & 3) * 32;        // warp row offset within tile
    int wn = (wid >> 2) * 64;       // warp col offset within tile
    int g = lane >> 2, tg = lane & 3;

    float acc[2][8][4];
    #pragma unroll
    for (int i = 0; i < 2; i++)
        #pragma unroll
        for (int j = 0; j < 8; j++)
            #pragma unroll
            for (int l = 0; l < 4; l++) acc[i][j][l] = 0.f;

    for (int k0 = 0; k0 < K; k0 += 16) {
        #pragma unroll
        for (int i = 0; i < 8; i++) {
            int idx = tid + i * 256;
            int m = idx >> 4, k = idx & 15;
            float v = 0.f;
            if (m0 + m < M && k0 + k < K) v = A[(size_t)(m0 + m) * K + (k0 + k)];
            As[m][k] = tf32r(v);
        }
        #pragma unroll
        for (int i = 0; i < 8; i++) {
            int idx = tid + i * 256;
            int k = idx >> 7, n = idx & 127;
            Bs[k][n] = (k0 + k < K) ? BT[(k0 + k) * HD + n] : 0.f;
        }
        __syncthreads();
        #pragma unroll
        for (int kk = 0; kk < 16; kk += 8) {
            float a[2][4];
            #pragma unroll
            for (int mt = 0; mt < 2; mt++) {
                int r = wm + mt * 16;
                a[mt][0] = As[r + g][kk + tg];
                a[mt][1] = As[r + g + 8][kk + tg];
                a[mt][2] = As[r + g][kk + tg + 4];
                a[mt][3] = As[r + g + 8][kk + tg + 4];
            }
            #pragma unroll
            for (int nt = 0; nt < 8; nt++) {
                float b0 = Bs[kk + tg][wn + nt * 8 + g];
                float b1 = Bs[kk + tg + 4][wn + nt * 8 + g];
                mma8(acc[0][nt], a[0], b0, b1);
                mma8(acc[1][nt], a[1], b0, b1);
            }
        }
        __syncthreads();
    }

    #pragma unroll
    for (int mt = 0; mt < 2; mt++) {
        int r = m0 + wm + mt * 16 + g;
        #pragma unroll
        for (int nt = 0; nt < 8; nt++) {
            int col = wn + nt * 8 + 2 * tg;
            if (r < M)
                *reinterpret_cast<float2*>(&C[(size_t)r * HD + col]) =
                    make_float2(acc[mt][nt][0], acc[mt][nt][1]);
            if (r + 8 < M)
                *reinterpret_cast<float2*>(&C[(size_t)(r + 8) * HD + col]) =
                    make_float2(acc[mt][nt][2], acc[mt][nt][3]);
        }
    }
}

// h1[i] = relu((P[i] + P[n0] + P[n1] + P[n2]) / 4)   (warp per node, float4 lanes)
__global__ __launch_bounds__(256)
void k_agg1(const int* __restrict__ neigh1, int M) {
    int node = blockIdx.x * 8 + (threadIdx.x >> 5);
    if (node >= M) return;
    int lane = threadIdx.x & 31;
    int n0 = __ldg(&neigh1[node * 3 + 0]);
    int n1 = __ldg(&neigh1[node * 3 + 1]);
    int n2 = __ldg(&neigh1[node * 3 + 2]);
    const float4* P4 = reinterpret_cast<const float4*>(g_P);
    float4 a = P4[(size_t)node * 32 + lane];
    float4 b = P4[(size_t)n0 * 32 + lane];
    float4 c = P4[(size_t)n1 * 32 + lane];
    float4 d = P4[(size_t)n2 * 32 + lane];
    float4 r;
    r.x = fmaxf((a.x + b.x + c.x + d.x) * 0.25f, 0.f);
    r.y = fmaxf((a.y + b.y + c.y + d.y) * 0.25f, 0.f);
    r.z = fmaxf((a.z + b.z + c.z + d.z) * 0.25f, 0.f);
    r.w = fmaxf((a.w + b.w + c.w + d.w) * 0.25f, 0.f);
    reinterpret_cast<float4*>(g_h1)[(size_t)node * 32 + lane] = r;
}

// Per batch item: v = relu(avg4 of gathered Q rows); scores = Wc @ v; log_softmax.
// Warp per item, 8 items per warp-slot loop, Wc cached in smem.
__global__ __launch_bounds__(256)
void k_out(const float* __restrict__ Wc, const int* __restrict__ neigh2,
           const int* __restrict__ nodes, float* __restrict__ out, int Bn) {
    __shared__ float4 Wcs[CD * 32];
    const float4* Wc4 = reinterpret_cast<const float4*>(Wc);
    for (int i = threadIdx.x; i < CD * 32; i += 256) Wcs[i] = Wc4[i];
    __syncthreads();

    int lane = threadIdx.x & 31;
    int wbase = blockIdx.x * 64 + (threadIdx.x >> 5);
    const float4* Q4 = reinterpret_cast<const float4*>(g_Q);

    for (int it = 0; it < 8; it++) {
        int item = wbase + it * 8;
        if (item >= Bn) continue;   // warp-uniform
        int gn = __ldg(&nodes[item]);
        int n0 = __ldg(&neigh2[gn * 3 + 0]);
        int n1 = __ldg(&neigh2[gn * 3 + 1]);
        int n2 = __ldg(&neigh2[gn * 3 + 2]);
        float4 a = Q4[(size_t)gn * 32 + lane];
        float4 b = Q4[(size_t)n0 * 32 + lane];
        float4 c = Q4[(size_t)n1 * 32 + lane];
        float4 d = Q4[(size_t)n2 * 32 + lane];
        float4 v;
        v.x = fmaxf((a.x + b.x + c.x + d.x) * 0.25f, 0.f);
        v.y = fmaxf((a.y + b.y + c.y + d.y) * 0.25f, 0.f);
        v.z = fmaxf((a.z + b.z + c.z + d.z) * 0.25f, 0.f);
        v.w = fmaxf((a.w + b.w + c.w + d.w) * 0.25f, 0.f);

        float s0 = 0.f, s1 = 0.f;
        for (int cc = 0; cc < CD; cc++) {
            float4 w = Wcs[cc * 32 + lane];
            float s = v.x * w.x + v.y * w.y + v.z * w.z + v.w * w.w;
            s += __shfl_xor_sync(0xffffffffu, s, 16);
            s += __shfl_xor_sync(0xffffffffu, s, 8);
            s += __shfl_xor_sync(0xffffffffu, s, 4);
            s += __shfl_xor_sync(0xffffffffu, s, 2);
            s += __shfl_xor_sync(0xffffffffu, s, 1);
            if (cc < 32) { if (lane == cc) s0 = s; }
            else if (lane == cc - 32) s1 = s;
        }
        float x1 = (lane < CD - 32) ? s1 : -INFINITY;
        float m = fmaxf(s0, x1);
        #pragma unroll
        for (int o = 16; o; o >>= 1) m = fmaxf(m, __shfl_xor_sync(0xffffffffu, m, o));
        float e = expf(s0 - m) + ((lane < CD - 32) ? expf(x1 - m) : 0.f);
        #pragma unroll
        for (int o = 16; o; o >>= 1) e += __shfl_xor_sync(0xffffffffu, e, o);
        float L = m + logf(e);
        out[(size_t)item * CD + lane] = s0 - L;
        if (lane < CD - 32) out[(size_t)item * CD + 32 + lane] = x1 - L;
    }
}

extern "C" void kernel_launch(void* const* d_in, const int* in_sizes, int n_in,
                              void* d_out, int out_size) {
    const float* features = (const float*)d_in[0];
    const float* W1       = (const float*)d_in[1];
    const float* W2       = (const float*)d_in[2];
    const float* Wc       = (const float*)d_in[3];
    const int*   neigh1   = (const int*)d_in[4];
    const int*   neigh2   = (const int*)d_in[5];
    const int*   nodes    = (const int*)d_in[6];
    float* out = (float*)d_out;

    int M  = in_sizes[0] / FD;   // 150000
    int Bn = in_sizes[6];        // 100000
    int mtiles = (M + 127) / 128;

    k_prep_bt<<<(FD * HD + 255) / 256, 256>>>(W1, FD, 0);
    k_prep_bt<<<(HD * HD + 255) / 256, 256>>>(W2, HD, 1);
    k_gemm_tf32<<<mtiles, 256>>>(features, M, FD, 0);   // P = feat @ W1^T
    k_agg1<<<(M + 7) / 8, 256>>>(neigh1, M);            // h1
    k_gemm_tf32<<<mtiles, 256>>>(nullptr, M, HD, 1);    // Q = h1 @ W2^T
    k_out<<<(Bn + 63) / 64, 256>>>(Wc, neigh2, nodes, out, Bn);
}

// round 4
// speedup vs baseline: 1.6967x; 1.6967x over previous
#include <cuda_runtime.h>
#include <math.h>
#include <stdint.h>

#define NN 150000
#define FD 602
#define HD 128
#define CD 41

#define MT 256          // CTA M tile
#define NT 128          // CTA N tile (= HD)
#define KC 32           // K chunk per stage
#define STAGES 3
#define RP 36           // smem row pitch in floats (bank-conflict-free, 16B-aligned rows)
#define STAGE_FLOATS ((MT + NT) * RP)
#define SMEM_BYTES (STAGES * STAGE_FLOATS * 4)   // 165888

// Scratch (device globals: no allocation allowed anywhere)
__device__ float g_P[(size_t)NN * HD];     // features @ W1^T
__device__ float g_h1[(size_t)NN * HD];    // relu(avg4(P))
__device__ float g_Q[(size_t)NN * HD];     // h1 @ W2^T

__device__ __forceinline__ void mma8(float* c, const float* a, float b0, float b1) {
    asm volatile(
        "mma.sync.aligned.m16n8k8.row.col.f32.tf32.tf32.f32 "
        "{%0,%1,%2,%3}, {%4,%5,%6,%7}, {%8,%9}, {%0,%1,%2,%3};\n"
        : "+f"(c[0]), "+f"(c[1]), "+f"(c[2]), "+f"(c[3])
        : "r"(__float_as_uint(a[0])), "r"(__float_as_uint(a[1])),
          "r"(__float_as_uint(a[2])), "r"(__float_as_uint(a[3])),
          "r"(__float_as_uint(b0)), "r"(__float_as_uint(b1)));
}

__device__ __forceinline__ uint32_t smem_u32(const void* p) {
    uint32_t a;
    asm("{ .reg .u64 t; cvta.to.shared.u64 t, %1; cvt.u32.u64 %0, t; }" : "=r"(a) : "l"(p));
    return a;
}
__device__ __forceinline__ void cp8(uint32_t dst, const float* src, uint32_t valid) {
    asm volatile("cp.async.ca.shared.global [%0], [%1], 8, %2;"
                 :: "r"(dst), "l"(src), "r"(valid) : "memory");
}
#define CP_COMMIT() asm volatile("cp.async.commit_group;" ::: "memory")
#define CP_WAIT1()  asm volatile("cp.async.wait_group 1;" ::: "memory")

// Stage one K-chunk: A rows [m0,m0+256) cols [k0,k0+32), B rows [0,128) same cols.
// 8-byte pieces (feature row stride 2408B is only 8B-aligned), zfill at K edge / M edge.
__device__ __forceinline__ void stage_chunk(uint32_t sbase, const float* __restrict__ A,
                                            const float* __restrict__ B, int m0, int M,
                                            int K, int k0, int tid) {
    #pragma unroll
    for (int i = 0; i < (MT + NT) * 16 / 256; i++) {   // 24 pieces per thread
        int p = tid + i * 256;
        int row = p >> 4, j = p & 15;
        int gk = k0 + j * 2;
        uint32_t dst = sbase + (uint32_t)(row * RP * 4 + j * 8);
        int rem = (K - gk) * 4;
        uint32_t valid = (uint32_t)min(max(rem, 0), 8);
        if (row < MT) {
            int grow = m0 + row;
            const float* src = A + ((grow < M) ? ((size_t)grow * K + min(gk, K - 1))
                                               : (size_t)0);
            if (grow >= M) valid = 0;
            cp8(dst, src, valid);
        } else {
            int n = row - MT;
            const float* src = B + (size_t)n * K + min(gk, K - 1);
            cp8(dst, src, valid);
        }
    }
}

// C[M][128] = A[M][K] @ B[128][K]^T  (tf32 mma.sync, cp.async 3-stage pipeline)
// mode 0: A=Aext(features), C=g_P;  mode 1: A=g_h1, C=g_Q.
__global__ __launch_bounds__(256, 1)
void k_gemm(const float* __restrict__ Aext, const float* __restrict__ B,
            int M, int K, int mode) {
    extern __shared__ float smem[];
    const float* __restrict__ A = mode ? g_h1 : Aext;
    float* __restrict__ C       = mode ? g_Q : g_P;

    int tid = threadIdx.x, wid = tid >> 5, lane = tid & 31;
    int g = lane >> 2, tg = lane & 3;
    int wm = (wid >> 1) * 64, wn = (wid & 1) * 64;     // warp tile 64x64
    int m0 = blockIdx.x * MT;
    uint32_t sb = smem_u32(smem);
    int nc = (K + KC - 1) / KC;

    float acc[4][8][4];
    #pragma unroll
    for (int a = 0; a < 4; a++)
        #pragma unroll
        for (int b = 0; b < 8; b++)
            #pragma unroll
            for (int d = 0; d < 4; d++) acc[a][b][d] = 0.f;

    // Prologue: stages 0,1
    stage_chunk(sb, A, B, m0, M, K, 0, tid);
    CP_COMMIT();
    if (nc > 1) stage_chunk(sb + STAGE_FLOATS * 4, A, B, m0, M, K, KC, tid);
    CP_COMMIT();

    for (int c = 0; c < nc; c++) {
        CP_WAIT1();
        __syncthreads();

        const float* sA = smem + (c % STAGES) * STAGE_FLOATS;
        const float* sB = sA + MT * RP;

        #pragma unroll
        for (int kk = 0; kk < KC; kk += 8) {
            float af[4][4], bf[8][2];
            #pragma unroll
            for (int mt = 0; mt < 4; mt++) {
                int r = wm + mt * 16;
                af[mt][0] = sA[(r + g) * RP + kk + tg];
                af[mt][1] = sA[(r + g + 8) * RP + kk + tg];
                af[mt][2] = sA[(r + g) * RP + kk + tg + 4];
                af[mt][3] = sA[(r + g + 8) * RP + kk + tg + 4];
            }
            #pragma unroll
            for (int nt = 0; nt < 8; nt++) {
                bf[nt][0] = sB[(wn + nt * 8 + g) * RP + kk + tg];
                bf[nt][1] = sB[(wn + nt * 8 + g) * RP + kk + tg + 4];
            }
            #pragma unroll
            for (int mt = 0; mt < 4; mt++)
                #pragma unroll
                for (int nt = 0; nt < 8; nt++)
                    mma8(acc[mt][nt], af[mt], bf[nt][0], bf[nt][1]);
        }

        if (c + 2 < nc)
            stage_chunk(sb + ((c + 2) % STAGES) * STAGE_FLOATS * 4, A, B, m0, M, K,
                        (c + 2) * KC, tid);
        CP_COMMIT();
        __syncthreads();
    }

    // Epilogue: float2 stores, M-guarded
    #pragma unroll
    for (int mt = 0; mt < 4; mt++) {
        int r0 = m0 + wm + mt * 16 + g;
        #pragma unroll
        for (int nt = 0; nt < 8; nt++) {
            int col = wn + nt * 8 + 2 * tg;
            if (r0 < M)
                *reinterpret_cast<float2*>(&C[(size_t)r0 * HD + col]) =
                    make_float2(acc[mt][nt][0], acc[mt][nt][1]);
            if (r0 + 8 < M)
                *reinterpret_cast<float2*>(&C[(size_t)(r0 + 8) * HD + col]) =
                    make_float2(acc[mt][nt][2], acc[mt][nt][3]);
        }
    }
}

// h1[i] = relu((P[i] + P[n0] + P[n1] + P[n2]) / 4)   (warp per node, float4 lanes)
__global__ __launch_bounds__(256)
void k_agg1(const int* __restrict__ neigh1, int M) {
    int node = blockIdx.x * 8 + (threadIdx.x >> 5);
    if (node >= M) return;
    int lane = threadIdx.x & 31;
    int n0 = __ldg(&neigh1[node * 3 + 0]);
    int n1 = __ldg(&neigh1[node * 3 + 1]);
    int n2 = __ldg(&neigh1[node * 3 + 2]);
    const float4* P4 = reinterpret_cast<const float4*>(g_P);
    float4 a = P4[(size_t)node * 32 + lane];
    float4 b = P4[(size_t)n0 * 32 + lane];
    float4 c = P4[(size_t)n1 * 32 + lane];
    float4 d = P4[(size_t)n2 * 32 + lane];
    float4 r;
    r.x = fmaxf((a.x + b.x + c.x + d.x) * 0.25f, 0.f);
    r.y = fmaxf((a.y + b.y + c.y + d.y) * 0.25f, 0.f);
    r.z = fmaxf((a.z + b.z + c.z + d.z) * 0.25f, 0.f);
    r.w = fmaxf((a.w + b.w + c.w + d.w) * 0.25f, 0.f);
    reinterpret_cast<float4*>(g_h1)[(size_t)node * 32 + lane] = r;
}

// Per batch item: v = relu(avg4 gathered Q rows); scores = Wc @ v; log_softmax.
__global__ __launch_bounds__(256)
void k_out(const float* __restrict__ Wc, const int* __restrict__ neigh2,
           const int* __restrict__ nodes, float* __restrict__ out, int Bn) {
    __shared__ float4 Wcs[CD * 32];
    const float4* Wc4 = reinterpret_cast<const float4*>(Wc);
    for (int i = threadIdx.x; i < CD * 32; i += 256) Wcs[i] = Wc4[i];
    __syncthreads();

    int lane = threadIdx.x & 31;
    int wbase = blockIdx.x * 64 + (threadIdx.x >> 5);
    const float4* Q4 = reinterpret_cast<const float4*>(g_Q);

    for (int it = 0; it < 8; it++) {
        int item = wbase + it * 8;
        if (item >= Bn) continue;   // warp-uniform
        int gn = __ldg(&nodes[item]);
        int n0 = __ldg(&neigh2[gn * 3 + 0]);
        int n1 = __ldg(&neigh2[gn * 3 + 1]);
        int n2 = __ldg(&neigh2[gn * 3 + 2]);
        float4 a = Q4[(size_t)gn * 32 + lane];
        float4 b = Q4[(size_t)n0 * 32 + lane];
        float4 c = Q4[(size_t)n1 * 32 + lane];
        float4 d = Q4[(size_t)n2 * 32 + lane];
        float4 v;
        v.x = fmaxf((a.x + b.x + c.x + d.x) * 0.25f, 0.f);
        v.y = fmaxf((a.y + b.y + c.y + d.y) * 0.25f, 0.f);
        v.z = fmaxf((a.z + b.z + c.z + d.z) * 0.25f, 0.f);
        v.w = fmaxf((a.w + b.w + c.w + d.w) * 0.25f, 0.f);

        float s0 = 0.f, s1 = 0.f;
        for (int cc = 0; cc < CD; cc++) {
            float4 w = Wcs[cc * 32 + lane];
            float s = v.x * w.x + v.y * w.y + v.z * w.z + v.w * w.w;
            s += __shfl_xor_sync(0xffffffffu, s, 16);
            s += __shfl_xor_sync(0xffffffffu, s, 8);
            s += __shfl_xor_sync(0xffffffffu, s, 4);
            s += __shfl_xor_sync(0xffffffffu, s, 2);
            s += __shfl_xor_sync(0xffffffffu, s, 1);
            if (cc < 32) { if (lane == cc) s0 = s; }
            else if (lane == cc - 32) s1 = s;
        }
        float x1 = (lane < CD - 32) ? s1 : -INFINITY;
        float m = fmaxf(s0, x1);
        #pragma unroll
        for (int o = 16; o; o >>= 1) m = fmaxf(m, __shfl_xor_sync(0xffffffffu, m, o));
        float e = expf(s0 - m) + ((lane < CD - 32) ? expf(x1 - m) : 0.f);
        #pragma unroll
        for (int o = 16; o; o >>= 1) e += __shfl_xor_sync(0xffffffffu, e, o);
        float L = m + logf(e);
        out[(size_t)item * CD + lane] = s0 - L;
        if (lane < CD - 32) out[(size_t)item * CD + 32 + lane] = x1 - L;
    }
}

extern "C" void kernel_launch(void* const* d_in, const int* in_sizes, int n_in,
                              void* d_out, int out_size) {
    const float* features = (const float*)d_in[0];
    const float* W1       = (const float*)d_in[1];
    const float* W2       = (const float*)d_in[2];
    const float* Wc       = (const float*)d_in[3];
    const int*   neigh1   = (const int*)d_in[4];
    const int*   neigh2   = (const int*)d_in[5];
    const int*   nodes    = (const int*)d_in[6];
    float* out = (float*)d_out;

    int M  = in_sizes[0] / FD;   // 150000
    int Bn = in_sizes[6];        // 100000
    int mtiles = (M + MT - 1) / MT;

    cudaFuncSetAttribute(k_gemm, cudaFuncAttributeMaxDynamicSharedMemorySize, SMEM_BYTES);

    k_gemm<<<mtiles, 256, SMEM_BYTES>>>(features, W1, M, FD, 0);  // P = feat @ W1^T
    k_agg1<<<(M + 7) / 8, 256>>>(neigh1, M);                      // h1 = relu(avg4 P)
    k_gemm<<<mtiles, 256, SMEM_BYTES>>>(nullptr, W2, M, HD, 1);   // Q = h1 @ W2^T
    k_out<<<(Bn + 63) / 64, 256>>>(Wc, neigh2, nodes, out, Bn);
}

// round 5
// speedup vs baseline: 1.9464x; 1.1472x over previous
#include <cuda_runtime.h>
#include <math.h>
#include <stdint.h>

#define NN 150000
#define FD 602
#define HD 128
#define CD 41

#define MT 256          // CTA M tile (gemm)
#define NT 128          // CTA N tile (= HD)
#define KC 32           // K chunk per stage
#define STAGES 4
#define RP 36           // smem row pitch (floats), bank-conflict-free
#define STAGE_FLOATS ((MT + NT) * RP)
#define SMEM_BYTES (STAGES * STAGE_FLOATS * 4)   // 221184

#define SB 128          // k_score items per CTA
#define SN 48           // padded class count
#define SP 132          // k_score smem pitch (floats)
#define SCORE_SMEM ((SB + SN) * SP * 4)          // 92928

// Scratch (device globals: no allocation allowed anywhere)
__device__ float g_P[(size_t)NN * HD];     // features @ W1^T
__device__ float g_h1[(size_t)NN * HD];    // relu(avg4(P))
__device__ float g_Q[(size_t)NN * HD];     // h1 @ W2^T

__device__ __forceinline__ void mma8(float* c, const float* a, float b0, float b1) {
    asm volatile(
        "mma.sync.aligned.m16n8k8.row.col.f32.tf32.tf32.f32 "
        "{%0,%1,%2,%3}, {%4,%5,%6,%7}, {%8,%9}, {%0,%1,%2,%3};\n"
        : "+f"(c[0]), "+f"(c[1]), "+f"(c[2]), "+f"(c[3])
        : "r"(__float_as_uint(a[0])), "r"(__float_as_uint(a[1])),
          "r"(__float_as_uint(a[2])), "r"(__float_as_uint(a[3])),
          "r"(__float_as_uint(b0)), "r"(__float_as_uint(b1)));
}
__device__ __forceinline__ uint32_t smem_u32(const void* p) {
    uint32_t a;
    asm("{ .reg .u64 t; cvta.to.shared.u64 t, %1; cvt.u32.u64 %0, t; }" : "=r"(a) : "l"(p));
    return a;
}
__device__ __forceinline__ void cp8(uint32_t dst, const float* src, uint32_t valid) {
    asm volatile("cp.async.ca.shared.global [%0], [%1], 8, %2;"
                 :: "r"(dst), "l"(src), "r"(valid) : "memory");
}
#define CP_COMMIT() asm volatile("cp.async.commit_group;" ::: "memory")
#define CP_WAIT2()  asm volatile("cp.async.wait_group 2;" ::: "memory")

// Stage one K-chunk: A rows [m0,m0+256) cols [k0,k0+32), B rows [0,128) same cols.
__device__ __forceinline__ void stage_chunk(uint32_t sbase, const float* __restrict__ A,
                                            const float* __restrict__ B, int m0, int M,
                                            int K, int k0, int tid) {
    #pragma unroll
    for (int i = 0; i < (MT + NT) * 16 / 256; i++) {   // 24 pieces per thread
        int p = tid + i * 256;
        int row = p >> 4, j = p & 15;
        int gk = k0 + j * 2;
        uint32_t dst = sbase + (uint32_t)(row * RP * 4 + j * 8);
        int rem = (K - gk) * 4;
        uint32_t valid = (uint32_t)min(max(rem, 0), 8);
        if (row < MT) {
            int grow = m0 + row;
            const float* src = A + ((grow < M) ? ((size_t)grow * K + min(gk, K - 1))
                                               : (size_t)0);
            if (grow >= M) valid = 0;
            cp8(dst, src, valid);
        } else {
            int n = row - MT;
            cp8(dst, B + (size_t)n * K + min(gk, K - 1), valid);
        }
    }
}

// C[M][128] = A[M][K] @ B[128][K]^T  (tf32 mma.sync, cp.async 4-stage, 1 sync/iter)
__global__ __launch_bounds__(256, 1)
void k_gemm(const float* __restrict__ Aext, const float* __restrict__ B,
            int M, int K, int mode) {
    extern __shared__ float smem[];
    const float* __restrict__ A = mode ? g_h1 : Aext;
    float* __restrict__ C       = mode ? g_Q : g_P;

    int tid = threadIdx.x, wid = tid >> 5, lane = tid & 31;
    int g = lane >> 2, tg = lane & 3;
    int wm = (wid >> 1) * 64, wn = (wid & 1) * 64;     // warp tile 64x64
    int m0 = blockIdx.x * MT;
    uint32_t sb = smem_u32(smem);
    int nc = (K + KC - 1) / KC;

    float acc[4][8][4];
    #pragma unroll
    for (int a = 0; a < 4; a++)
        #pragma unroll
        for (int b = 0; b < 8; b++)
            #pragma unroll
            for (int d = 0; d < 4; d++) acc[a][b][d] = 0.f;

    // Prologue: stages 0..2
    #pragma unroll
    for (int s = 0; s < 3; s++) {
        if (s < nc) stage_chunk(sb + (uint32_t)s * STAGE_FLOATS * 4, A, B, m0, M, K, s * KC, tid);
        CP_COMMIT();
    }

    for (int c = 0; c < nc; c++) {
        CP_WAIT2();
        __syncthreads();

        const float* sA = smem + (c % STAGES) * STAGE_FLOATS;
        const float* sB = sA + MT * RP;

        #pragma unroll
        for (int kk = 0; kk < KC; kk += 8) {
            float af[4][4], bf[8][2];
            #pragma unroll
            for (int mt = 0; mt < 4; mt++) {
                int r = wm + mt * 16;
                af[mt][0] = sA[(r + g) * RP + kk + tg];
                af[mt][1] = sA[(r + g + 8) * RP + kk + tg];
                af[mt][2] = sA[(r + g) * RP + kk + tg + 4];
                af[mt][3] = sA[(r + g + 8) * RP + kk + tg + 4];
            }
            #pragma unroll
            for (int nt = 0; nt < 8; nt++) {
                bf[nt][0] = sB[(wn + nt * 8 + g) * RP + kk + tg];
                bf[nt][1] = sB[(wn + nt * 8 + g) * RP + kk + tg + 4];
            }
            #pragma unroll
            for (int mt = 0; mt < 4; mt++)
                #pragma unroll
                for (int nt = 0; nt < 8; nt++)
                    mma8(acc[mt][nt], af[mt], bf[nt][0], bf[nt][1]);
        }

        if (c + 3 < nc)
            stage_chunk(sb + (uint32_t)((c + 3) % STAGES) * STAGE_FLOATS * 4, A, B,
                        m0, M, K, (c + 3) * KC, tid);
        CP_COMMIT();
    }

    #pragma unroll
    for (int mt = 0; mt < 4; mt++) {
        int r0 = m0 + wm + mt * 16 + g;
        #pragma unroll
        for (int nt = 0; nt < 8; nt++) {
            int col = wn + nt * 8 + 2 * tg;
            if (r0 < M)
                *reinterpret_cast<float2*>(&C[(size_t)r0 * HD + col]) =
                    make_float2(acc[mt][nt][0], acc[mt][nt][1]);
            if (r0 + 8 < M)
                *reinterpret_cast<float2*>(&C[(size_t)(r0 + 8) * HD + col]) =
                    make_float2(acc[mt][nt][2], acc[mt][nt][3]);
        }
    }
}

// h1[i] = relu((P[i] + P[n0] + P[n1] + P[n2]) / 4)   (warp per node, float4 lanes)
__global__ __launch_bounds__(256)
void k_agg1(const int* __restrict__ neigh1, int M) {
    int node = blockIdx.x * 8 + (threadIdx.x >> 5);
    if (node >= M) return;
    int lane = threadIdx.x & 31;
    int n0 = __ldg(&neigh1[node * 3 + 0]);
    int n1 = __ldg(&neigh1[node * 3 + 1]);
    int n2 = __ldg(&neigh1[node * 3 + 2]);
    const float4* P4 = reinterpret_cast<const float4*>(g_P);
    float4 a = P4[(size_t)node * 32 + lane];
    float4 b = P4[(size_t)n0 * 32 + lane];
    float4 c = P4[(size_t)n1 * 32 + lane];
    float4 d = P4[(size_t)n2 * 32 + lane];
    float4 r;
    r.x = fmaxf((a.x + b.x + c.x + d.x) * 0.25f, 0.f);
    r.y = fmaxf((a.y + b.y + c.y + d.y) * 0.25f, 0.f);
    r.z = fmaxf((a.z + b.z + c.z + d.z) * 0.25f, 0.f);
    r.w = fmaxf((a.w + b.w + c.w + d.w) * 0.25f, 0.f);
    reinterpret_cast<float4*>(g_h1)[(size_t)node * 32 + lane] = r;
}

// Fused: gather Q rows (avg4+relu) -> smem; tf32 mma scores vs Wc; log-softmax in
// fragments; store. CTA = 128 items, 8 warps x m16, N=48 (cols >=41 masked).
__global__ __launch_bounds__(256, 2)
void k_score(const float* __restrict__ Wc, const int* __restrict__ neigh2,
             const int* __restrict__ nodes, float* __restrict__ out, int Bn) {
    extern __shared__ float smem[];
    float* sA = smem;               // [SB][SP]
    float* sB = smem + SB * SP;     // [SN][SP]

    int tid = threadIdx.x, wid = tid >> 5, lane = tid & 31;
    int g = lane >> 2, tg = lane & 3;
    int blk0 = blockIdx.x * SB;
    const float4* Q4 = reinterpret_cast<const float4*>(g_Q);

    // Wc -> smem (rows 41..47 zero)
    for (int idx = tid; idx < SN * HD; idx += 256) {
        int r = idx >> 7, c = idx & 127;
        sB[r * SP + c] = (r < CD) ? __ldg(&Wc[r * HD + c]) : 0.f;
    }

    // Gather phase: warp handles 16 items
    for (int i = 0; i < 16; i++) {
        int il = wid * 16 + i;
        int item = blk0 + il;
        float4 v = make_float4(0.f, 0.f, 0.f, 0.f);
        if (item < Bn) {
            int gn = __ldg(&nodes[item]);
            int n0 = __ldg(&neigh2[gn * 3 + 0]);
            int n1 = __ldg(&neigh2[gn * 3 + 1]);
            int n2 = __ldg(&neigh2[gn * 3 + 2]);
            float4 a = Q4[(size_t)gn * 32 + lane];
            float4 b = Q4[(size_t)n0 * 32 + lane];
            float4 c = Q4[(size_t)n1 * 32 + lane];
            float4 d = Q4[(size_t)n2 * 32 + lane];
            v.x = fmaxf((a.x + b.x + c.x + d.x) * 0.25f, 0.f);
            v.y = fmaxf((a.y + b.y + c.y + d.y) * 0.25f, 0.f);
            v.z = fmaxf((a.z + b.z + c.z + d.z) * 0.25f, 0.f);
            v.w = fmaxf((a.w + b.w + c.w + d.w) * 0.25f, 0.f);
        }
        *reinterpret_cast<float4*>(&sA[il * SP + lane * 4]) = v;
    }
    __syncthreads();

    // MMA phase: warp w -> rows w*16 + {g, g+8}, all 48 cols
    float acc[6][4];
    #pragma unroll
    for (int f = 0; f < 6; f++)
        #pragma unroll
        for (int d = 0; d < 4; d++) acc[f][d] = 0.f;

    int rbase = wid * 16;
    #pragma unroll
    for (int kk = 0; kk < HD; kk += 8) {
        float af[4];
        af[0] = sA[(rbase + g) * SP + kk + tg];
        af[1] = sA[(rbase + g + 8) * SP + kk + tg];
        af[2] = sA[(rbase + g) * SP + kk + tg + 4];
        af[3] = sA[(rbase + g + 8) * SP + kk + tg + 4];
        #pragma unroll
        for (int f = 0; f < 6; f++) {
            float b0 = sB[(f * 8 + g) * SP + kk + tg];
            float b1 = sB[(f * 8 + g) * SP + kk + tg + 4];
            mma8(acc[f], af, b0, b1);
        }
    }

    // Log-softmax per row within the lane quad (tg = lane&3; xor 1,2 stays in quad)
    #pragma unroll
    for (int rh = 0; rh < 2; rh++) {
        float m = -INFINITY;
        #pragma unroll
        for (int f = 0; f < 6; f++) {
            int c0 = f * 8 + 2 * tg;
            float v0 = acc[f][2 * rh], v1 = acc[f][2 * rh + 1];
            if (c0 < CD) m = fmaxf(m, v0);
            if (c0 + 1 < CD) m = fmaxf(m, v1);
        }
        m = fmaxf(m, __shfl_xor_sync(0xffffffffu, m, 1));
        m = fmaxf(m, __shfl_xor_sync(0xffffffffu, m, 2));
        float e = 0.f;
        #pragma unroll
        for (int f = 0; f < 6; f++) {
            int c0 = f * 8 + 2 * tg;
            float v0 = acc[f][2 * rh], v1 = acc[f][2 * rh + 1];
            if (c0 < CD) e += expf(v0 - m);
            if (c0 + 1 < CD) e += expf(v1 - m);
        }
        e += __shfl_xor_sync(0xffffffffu, e, 1);
        e += __shfl_xor_sync(0xffffffffu, e, 2);
        float L = m + logf(e);

        int item = blk0 + rbase + g + 8 * rh;
        if (item < Bn) {
            float* orow = out + (size_t)item * CD;
            #pragma unroll
            for (int f = 0; f < 6; f++) {
                int c0 = f * 8 + 2 * tg;
                if (c0 < CD) orow[c0] = acc[f][2 * rh] - L;
                if (c0 + 1 < CD) orow[c0 + 1] = acc[f][2 * rh + 1] - L;
            }
        }
    }
}

extern "C" void kernel_launch(void* const* d_in, const int* in_sizes, int n_in,
                              void* d_out, int out_size) {
    const float* features = (const float*)d_in[0];
    const float* W1       = (const float*)d_in[1];
    const float* W2       = (const float*)d_in[2];
    const float* Wc       = (const float*)d_in[3];
    const int*   neigh1   = (const int*)d_in[4];
    const int*   neigh2   = (const int*)d_in[5];
    const int*   nodes    = (const int*)d_in[6];
    float* out = (float*)d_out;

    int M  = in_sizes[0] / FD;   // 150000
    int Bn = in_sizes[6];        // 100000
    int mtiles = (M + MT - 1) / MT;

    cudaFuncSetAttribute(k_gemm, cudaFuncAttributeMaxDynamicSharedMemorySize, SMEM_BYTES);
    cudaFuncSetAttribute(k_score, cudaFuncAttributeMaxDynamicSharedMemorySize, SCORE_SMEM);

    k_gemm<<<mtiles, 256, SMEM_BYTES>>>(features, W1, M, FD, 0);  // P = feat @ W1^T
    k_agg1<<<(M + 7) / 8, 256>>>(neigh1, M);                      // h1 = relu(avg4 P)
    k_gemm<<<mtiles, 256, SMEM_BYTES>>>(nullptr, W2, M, HD, 1);   // Q = h1 @ W2^T
    k_score<<<(Bn + SB - 1) / SB, 256, SCORE_SMEM>>>(Wc, neigh2, nodes, out, Bn);
}